// round 11
// baseline (speedup 1.0000x reference)
#include <cuda_runtime.h>
#include <cuda_bf16.h>
#include <cstdint>

#define BATCH   2
#define CCH     64
#define NTOK    110592      // 48*48*48
#define KROWS   128
#define TN      128         // tile width (n columns)
#define TILES   864         // NTOK / TN per batch
#define NPB     74          // parts per batch -> grid 148
#define RAWS    132         // raw f32 row stride (floats)
#define SW2     68          // X2 row stride in u32 words (136 bf16)
#define RAWW    8448        // 64*RAWS (u32 words per raw buffer)
#define X2OFF   16896       // word offset of X2h
#define PLANEB  17408       // bytes between X2h and X2l (4352 words)
#define SREDOFF 25600       // word offset of sred (K1)

typedef uint32_t u32;

// ---------------- helpers ----------------
__device__ __forceinline__ float bhi(float v) {
    return __bfloat162float(__float2bfloat16_rn(v));
}
__device__ __forceinline__ u32 pk(float lo, float hi) {
    __nv_bfloat162 p = __floats2bfloat162_rn(lo, hi);   // .x = lo half
    return reinterpret_cast<u32&>(p);
}
__device__ __forceinline__ void sp2(float a, float b, u32& h, u32& l) {
    float ha = bhi(a), hb = bhi(b);
    h = pk(ha, hb);
    l = pk(a - ha, b - hb);
}
// lo-plane from already-packed hi reg (exact: bf16 bits<<16 == value)
__device__ __forceinline__ u32 losplit(u32 h, float a, float b) {
    float ha = __uint_as_float(h << 16);
    float hb = __uint_as_float(h & 0xffff0000u);
    return pk(a - ha, b - hb);
}
__device__ __forceinline__ void mma16(float (&d)[4], const u32 (&a)[4], u32 b0, u32 b1) {
    asm volatile("mma.sync.aligned.m16n8k16.row.col.f32.bf16.bf16.f32 "
                 "{%0,%1,%2,%3}, {%4,%5,%6,%7}, {%8,%9}, {%0,%1,%2,%3};"
                 : "+f"(d[0]), "+f"(d[1]), "+f"(d[2]), "+f"(d[3])
                 : "r"(a[0]), "r"(a[1]), "r"(a[2]), "r"(a[3]), "r"(b0), "r"(b1));
}
__device__ __forceinline__ void ldsm4t(u32& r0, u32& r1, u32& r2, u32& r3, u32 addr) {
    asm volatile("ldmatrix.sync.aligned.m8n8.x4.trans.shared.b16 {%0,%1,%2,%3}, [%4];"
                 : "=r"(r0), "=r"(r1), "=r"(r2), "=r"(r3) : "r"(addr));
}
__device__ __forceinline__ void ldsm4(u32& r0, u32& r1, u32& r2, u32& r3, u32 addr) {
    asm volatile("ldmatrix.sync.aligned.m8n8.x4.shared.b16 {%0,%1,%2,%3}, [%4];"
                 : "=r"(r0), "=r"(r1), "=r"(r2), "=r"(r3) : "r"(addr));
}
__device__ __forceinline__ void cpasync16(u32 dst, const void* src) {
    asm volatile("cp.async.cg.shared.global [%0], [%1], 16;" :: "r"(dst), "l"(src));
}
__device__ __forceinline__ void cp_commit() { asm volatile("cp.async.commit_group;"); }
__device__ __forceinline__ void cp_wait0()  { asm volatile("cp.async.wait_group 0;"); }
__device__ __forceinline__ void cp_wait1()  { asm volatile("cp.async.wait_group 1;"); }

// Scratch
__device__ float g_G_part[BATCH * NPB * KROWS * CCH];
__device__ float g_s_part[BATCH * NPB * KROWS];
__device__ float g_G[BATCH * KROWS * CCH];
__device__ float g_s[BATCH * KROWS];
__device__ float g_M[BATCH * CCH * CCH];

// cp.async one 64x128 f32 tile into raw buffer (word offset off)
__device__ __forceinline__ void tile_issue(u32 sbase, u32 off, const float* xb,
                                           int s, int tid) {
#pragma unroll
    for (int i = 0; i < 4; ++i) {
        int idx = i * 512 + tid;
        int row = idx >> 5, c16 = idx & 31;
        cpasync16(sbase + (off + (u32)(row * RAWS + c16 * 4)) * 4,
                  xb + (size_t)row * NTOK + (size_t)s * TN + c16 * 4);
    }
}

// stage raw f32 -> X2 hi/lo bf16 planes ([c][n], stride SW2)
__device__ __forceinline__ void tile_stage(const u32* sm, u32* X2h, u32* X2l,
                                           int cur, int wrp, int lane) {
    const float* rp = reinterpret_cast<const float*>(sm) + cur * RAWW;
    const int lc = 4 * wrp;
#pragma unroll
    for (int r = 0; r < 4; ++r) {
        float4 v = *reinterpret_cast<const float4*>(rp + (lc + r) * RAWS + 4 * lane);
        u32 h0 = pk(bhi(v.x), bhi(v.y));
        u32 h1 = pk(bhi(v.z), bhi(v.w));
        u32 l0 = losplit(h0, v.x, v.y);
        u32 l1 = losplit(h1, v.z, v.w);
        *reinterpret_cast<uint2*>(&X2h[(lc + r) * SW2 + 2 * lane]) = make_uint2(h0, h1);
        *reinterpret_cast<uint2*>(&X2l[(lc + r) * SW2 + 2 * lane]) = make_uint2(l0, l1);
    }
}

// ---------------------------------------------------------------------------
// Kernel 1: per 128-col tile: k = Wk*X (bf16x3), p = exp(k) in registers,
// G += P*X^T (bf16x3). Interleaved accumulator chains to hide HMMA latency.
// 16 warps: (ms 0..7 d-strip) x (nh 0..1 n-half). G halves combined via smem.
// ---------------------------------------------------------------------------
__global__ void __launch_bounds__(512, 1)
kv_ctx_kernel(const float* __restrict__ x, const float* __restrict__ wqkv)
{
    extern __shared__ __align__(16) u32 sm[];
    u32* X2h = sm + X2OFF;
    u32* X2l = sm + X2OFF + 4352;
    float* sred = reinterpret_cast<float*>(sm + SREDOFF);
    u32 sbase;
    asm("{ .reg .u64 t; cvta.to.shared.u64 t, %1; cvt.u32.u64 %0, t; }"
        : "=r"(sbase) : "l"(sm));

    const int tid  = threadIdx.x;
    const int wrp  = tid >> 5;
    const int lane = tid & 31;
    const int g    = lane >> 2;
    const int t    = lane & 3;
    const int ms   = wrp & 7;
    const int nh   = wrp >> 3;

    const int b    = blockIdx.x / NPB;
    const int part = blockIdx.x - b * NPB;
    const int s0   = (part * TILES) / NPB;
    const int s1   = ((part + 1) * TILES) / NPB;

    // Wk fragments (rows 128 + 16*ms .. +16), bf16 hi/lo
    u32 wh[4][4], wl[4][4];
    {
        const float* w0 = wqkv + (size_t)(128 + 16 * ms + g) * 64;
        const float* w1 = w0 + (size_t)8 * 64;
#pragma unroll
        for (int kc = 0; kc < 4; ++kc) {
            sp2(w0[16*kc + 2*t],     w0[16*kc + 2*t + 1], wh[kc][0], wl[kc][0]);
            sp2(w1[16*kc + 2*t],     w1[16*kc + 2*t + 1], wh[kc][1], wl[kc][1]);
            sp2(w0[16*kc + 2*t + 8], w0[16*kc + 2*t + 9], wh[kc][2], wl[kc][2]);
            sp2(w1[16*kc + 2*t + 8], w1[16*kc + 2*t + 9], wh[kc][3], wl[kc][3]);
        }
    }

    float ga[8][4];
#pragma unroll
    for (int cb = 0; cb < 8; ++cb) { ga[cb][0]=ga[cb][1]=ga[cb][2]=ga[cb][3]=0.f; }
    float srow0 = 0.f, srow1 = 0.f;

    // ldmatrix base byte-offsets (lane-dependent)
    const u32 X2hB = sbase + X2OFF * 4;
    const int r1l = lane & 15;                          // GEMM1 (trans): rows = c
    const int w1o = (lane >> 4) << 2;                   // n-word select
    const u32 a1base = X2hB + (u32)((r1l * SW2 + nh * 32 + w1o) * 4);
    const int r2l = ((lane >> 4) & 1) * 8 + (lane & 7); // GEMM2: rows = c
    const int w2o = ((lane >> 3) & 1) * 4;
    const u32 a2base = X2hB + (u32)((r2l * SW2 + nh * 32 + w2o) * 4);

    const float* xb = x + (size_t)b * CCH * NTOK;

    tile_issue(sbase, 0, xb, s0, tid);
    cp_commit();

    for (int s = s0; s < s1; ++s) {
        const int cur = (s - s0) & 1;
        if (s + 1 < s1) {
            tile_issue(sbase, (cur ^ 1) * RAWW, xb, s + 1, tid);
            cp_commit();
            cp_wait1();
        } else {
            cp_wait0();
        }
        __syncthreads();          // raw[cur] ready AND prev compute done
        tile_stage(sm, X2h, X2l, cur, wrp, lane);
        __syncthreads();

#pragma unroll
        for (int p = 0; p < 4; ++p) {
            // ---- GEMM1: 6 independent accumulator chains (hh/hl/lh x 2 nb) ----
            float Ca[4] = {0.f,0.f,0.f,0.f}, Cb[4] = {0.f,0.f,0.f,0.f};
            float Cc[4] = {0.f,0.f,0.f,0.f}, Cd[4] = {0.f,0.f,0.f,0.f};
            float Ce[4] = {0.f,0.f,0.f,0.f}, Cf[4] = {0.f,0.f,0.f,0.f};
#pragma unroll
            for (int kc = 0; kc < 4; ++kc) {
                const u32 ah = a1base + (u32)(kc * (16 * SW2 * 4) + p * 32);
                u32 h0,h1,h2,h3, l0,l1,l2,l3;
                ldsm4t(h0, h1, h2, h3, ah);
                ldsm4t(l0, l1, l2, l3, ah + PLANEB);
                mma16(Ca, wh[kc], h0, h1);
                mma16(Cb, wh[kc], h2, h3);
                mma16(Cc, wh[kc], l0, l1);
                mma16(Cd, wh[kc], l2, l3);
                mma16(Ce, wl[kc], h0, h1);
                mma16(Cf, wl[kc], h2, h3);
            }
            float C0[4], C1[4];
#pragma unroll
            for (int i = 0; i < 4; ++i) {
                C0[i] = (Ca[i] + Cc[i]) + Ce[i];
                C1[i] = (Cb[i] + Cd[i]) + Cf[i];
            }
            // ---- exp in registers -> P fragments ----
            float e00 = __expf(C0[0]), e01 = __expf(C0[1]);
            float e02 = __expf(C0[2]), e03 = __expf(C0[3]);
            float e10 = __expf(C1[0]), e11 = __expf(C1[1]);
            float e12 = __expf(C1[2]), e13 = __expf(C1[3]);
            srow0 += e00 + e01 + e10 + e11;
            srow1 += e02 + e03 + e12 + e13;
            u32 Ah[4], Al[4];
            Ah[0] = pk(bhi(e00), bhi(e01)); Al[0] = losplit(Ah[0], e00, e01);
            Ah[1] = pk(bhi(e02), bhi(e03)); Al[1] = losplit(Ah[1], e02, e03);
            Ah[2] = pk(bhi(e10), bhi(e11)); Al[2] = losplit(Ah[2], e10, e11);
            Ah[3] = pk(bhi(e12), bhi(e13)); Al[3] = losplit(Ah[3], e12, e13);
            // ---- GEMM2: G += P * X^T, pp pairs -> 4 chains between reuses ----
#pragma unroll
            for (int hf = 0; hf < 2; ++hf) {
                const u32 aA = a2base + (u32)((2*hf)     * (16 * SW2 * 4) + p * 32);
                const u32 aB = a2base + (u32)((2*hf + 1) * (16 * SW2 * 4) + p * 32);
                u32 Ah0,Ah1,Ah2,Ah3, Al0,Al1,Al2,Al3;
                u32 Bh0,Bh1,Bh2,Bh3, Bl0,Bl1,Bl2,Bl3;
                ldsm4(Ah0, Ah1, Ah2, Ah3, aA);
                ldsm4(Al0, Al1, Al2, Al3, aA + PLANEB);
                ldsm4(Bh0, Bh1, Bh2, Bh3, aB);
                ldsm4(Bl0, Bl1, Bl2, Bl3, aB + PLANEB);
                // per-accumulator order preserved: (Ah,h) (Ah,l) (Al,h)
                mma16(ga[4*hf+0], Ah, Ah0, Ah1);
                mma16(ga[4*hf+1], Ah, Ah2, Ah3);
                mma16(ga[4*hf+2], Ah, Bh0, Bh1);
                mma16(ga[4*hf+3], Ah, Bh2, Bh3);
                mma16(ga[4*hf+0], Ah, Al0, Al1);
                mma16(ga[4*hf+1], Ah, Al2, Al3);
                mma16(ga[4*hf+2], Ah, Bl0, Bl1);
                mma16(ga[4*hf+3], Ah, Bl2, Bl3);
                mma16(ga[4*hf+0], Al, Ah0, Ah1);
                mma16(ga[4*hf+1], Al, Ah2, Ah3);
                mma16(ga[4*hf+2], Al, Bh0, Bh1);
                mma16(ga[4*hf+3], Al, Bh2, Bh3);
            }
        }
    }

    // ---- s reduce ----
    srow0 += __shfl_xor_sync(0xffffffffu, srow0, 1);
    srow0 += __shfl_xor_sync(0xffffffffu, srow0, 2);
    srow1 += __shfl_xor_sync(0xffffffffu, srow1, 1);
    srow1 += __shfl_xor_sync(0xffffffffu, srow1, 2);
    if (t == 0) {
        sred[nh * 128 + 16 * ms + g]     = srow0;
        sred[nh * 128 + 16 * ms + g + 8] = srow1;
    }
    __syncthreads();

    // ---- combine G halves across nh via smem (reuse raw area) ----
    float* gred = reinterpret_cast<float*>(sm);
    const int r0 = 16 * ms + g, r1 = r0 + 8;
    if (nh == 1) {
#pragma unroll
        for (int cb = 0; cb < 8; ++cb) {
            const int col = cb * 8 + 2 * t;
            *reinterpret_cast<float2*>(&gred[r0 * 64 + col]) = make_float2(ga[cb][0], ga[cb][1]);
            *reinterpret_cast<float2*>(&gred[r1 * 64 + col]) = make_float2(ga[cb][2], ga[cb][3]);
        }
    }
    __syncthreads();
    if (nh == 0) {
        float* gp = g_G_part + (size_t)(b * NPB + part) * (KROWS * CCH);
#pragma unroll
        for (int cb = 0; cb < 8; ++cb) {
            const int col = cb * 8 + 2 * t;
            *reinterpret_cast<float2*>(gp + (size_t)r0 * CCH + col) =
                make_float2(ga[cb][0] + gred[r0 * 64 + col], ga[cb][1] + gred[r0 * 64 + col + 1]);
            *reinterpret_cast<float2*>(gp + (size_t)r1 * CCH + col) =
                make_float2(ga[cb][2] + gred[r1 * 64 + col], ga[cb][3] + gred[r1 * 64 + col + 1]);
        }
    }
    if (tid < KROWS)
        g_s_part[(size_t)(b * NPB + part) * KROWS + tid] = sred[tid] + sred[128 + tid];
}

// ---------------------------------------------------------------------------
// Kernel 2a: reduce partials over NPB parts
// ---------------------------------------------------------------------------
__global__ void __launch_bounds__(256)
reduce_G_kernel()
{
    const int b   = blockIdx.x >> 5;
    const int idx = (blockIdx.x & 31) * 256 + threadIdx.x;
    const float* p = g_G_part + (size_t)b * NPB * (KROWS * CCH) + idx;
    float acc = 0.f;
#pragma unroll 8
    for (int j = 0; j < NPB; ++j) acc += p[(size_t)j * (KROWS * CCH)];
    g_G[(size_t)b * (KROWS * CCH) + idx] = acc;

    if ((blockIdx.x & 31) == 0 && threadIdx.x < KROWS) {
        const float* q = g_s_part + (size_t)b * NPB * KROWS + threadIdx.x;
        float a2 = 0.f;
#pragma unroll 8
        for (int j = 0; j < NPB; ++j) a2 += q[j * KROWS];
        g_s[b * KROWS + threadIdx.x] = a2;
    }
}

// ---------------------------------------------------------------------------
// Kernel 2b: ctx -> T -> M  (tiny, one block per batch)
// ---------------------------------------------------------------------------
__global__ void __launch_bounds__(256)
proj_kernel(const float* __restrict__ wqkv, const float* __restrict__ wout)
{
    const int b   = blockIdx.x;
    const int tid = threadIdx.x;
    __shared__ float ctxn[KROWS * 32];
    __shared__ float Ts[KROWS * CCH];

    const float* Gb = g_G + (size_t)b * (KROWS * CCH);
    const float* sb = g_s + b * KROWS;

    for (int idx = tid; idx < KROWS * 32; idx += 256) {
        const int d = idx >> 5, e = idx & 31, h = d >> 5;
        const float* wv = wqkv + (size_t)(256 + h * 32 + e) * 64;
        const float* gr = Gb + (size_t)d * CCH;
        float acc = 0.f;
#pragma unroll 8
        for (int c = 0; c < CCH; ++c) acc = fmaf(wv[c], gr[c], acc);
        ctxn[idx] = acc / sb[d];
    }
    __syncthreads();

    for (int idx = tid; idx < KROWS * CCH; idx += 256) {
        const int o = idx >> 6, c = idx & 63;
        const int h = o >> 5, e = o & 31;
        float acc = 0.f;
#pragma unroll 8
        for (int dd = 0; dd < 32; ++dd)
            acc = fmaf(ctxn[((h * 32 + dd) << 5) + e], wqkv[(size_t)(h * 32 + dd) * 64 + c], acc);
        Ts[idx] = acc;
    }
    __syncthreads();

    for (int idx = tid; idx < CCH * CCH; idx += 256) {
        const int c1 = idx >> 6, c2 = idx & 63;
        float acc = 0.f;
#pragma unroll 8
        for (int o = 0; o < KROWS; ++o)
            acc = fmaf(wout[(size_t)c1 * KROWS + o], Ts[o * CCH + c2], acc);
        g_M[(size_t)b * (CCH * CCH) + idx] = acc;
    }
}

// ---------------------------------------------------------------------------
// Kernel 3: out = M*X + b_out. 16 warps = (ms 0..3) x (nh 0..3), TN=128.
// Interleaved 4-chain mma schedule (bitwise-identical accumulation order).
// ---------------------------------------------------------------------------
__global__ void __launch_bounds__(512, 1)
out_proj_kernel(const float* __restrict__ x, const float* __restrict__ bout,
                float* __restrict__ out)
{
    extern __shared__ __align__(16) u32 sm[];
    u32* X2h = sm + X2OFF;
    u32* X2l = sm + X2OFF + 4352;
    u32 sbase;
    asm("{ .reg .u64 t; cvta.to.shared.u64 t, %1; cvt.u32.u64 %0, t; }"
        : "=r"(sbase) : "l"(sm));

    const int tid  = threadIdx.x;
    const int wrp  = tid >> 5;
    const int lane = tid & 31;
    const int g    = lane >> 2;
    const int t    = lane & 3;
    const int ms   = wrp & 3;
    const int nh   = wrp >> 2;

    const int b    = blockIdx.x / NPB;
    const int part = blockIdx.x - b * NPB;
    const int s0   = (part * TILES) / NPB;
    const int s1   = ((part + 1) * TILES) / NPB;

    // M fragments
    u32 mh[4][4], ml[4][4];
    {
        const float* M0 = g_M + (size_t)b * (CCH * CCH) + (size_t)(16 * ms + g) * 64;
        const float* M1 = M0 + (size_t)8 * 64;
#pragma unroll
        for (int kc = 0; kc < 4; ++kc) {
            sp2(M0[16*kc + 2*t],     M0[16*kc + 2*t + 1], mh[kc][0], ml[kc][0]);
            sp2(M1[16*kc + 2*t],     M1[16*kc + 2*t + 1], mh[kc][1], ml[kc][1]);
            sp2(M0[16*kc + 2*t + 8], M0[16*kc + 2*t + 9], mh[kc][2], ml[kc][2]);
            sp2(M1[16*kc + 2*t + 8], M1[16*kc + 2*t + 9], mh[kc][3], ml[kc][3]);
        }
    }
    const float bias0 = bout[16 * ms + g];
    const float bias1 = bout[16 * ms + g + 8];

    const u32 X2hB = sbase + X2OFF * 4;
    const int r1l = lane & 15;
    const int w1o = (lane >> 4) << 2;
    const u32 a1base = X2hB + (u32)((r1l * SW2 + nh * 16 + w1o) * 4);

    const float* xb = x   + (size_t)b * CCH * NTOK;
    float*       ob = out + (size_t)b * CCH * NTOK;

    tile_issue(sbase, 0, xb, s0, tid);
    cp_commit();

    for (int s = s0; s < s1; ++s) {
        const int cur = (s - s0) & 1;
        if (s + 1 < s1) {
            tile_issue(sbase, (cur ^ 1) * RAWW, xb, s + 1, tid);
            cp_commit();
            cp_wait1();
        } else {
            cp_wait0();
        }
        __syncthreads();
        tile_stage(sm, X2h, X2l, cur, wrp, lane);
        __syncthreads();

        float C[4][4];
#pragma unroll
        for (int nb = 0; nb < 4; ++nb) { C[nb][0]=C[nb][1]=C[nb][2]=C[nb][3]=0.f; }
#pragma unroll
        for (int kc = 0; kc < 4; ++kc) {
            const u32 aA = a1base + (u32)(kc * (16 * SW2 * 4));
            const u32 aB = aA + 32;
            u32 Ah0,Ah1,Ah2,Ah3, Al0,Al1,Al2,Al3;
            u32 Bh0,Bh1,Bh2,Bh3, Bl0,Bl1,Bl2,Bl3;
            ldsm4t(Ah0, Ah1, Ah2, Ah3, aA);
            ldsm4t(Al0, Al1, Al2, Al3, aA + PLANEB);
            ldsm4t(Bh0, Bh1, Bh2, Bh3, aB);
            ldsm4t(Bl0, Bl1, Bl2, Bl3, aB + PLANEB);
            // interleave 4 chains; per-chain order (mh,h)(mh,l)(ml,h) preserved
            mma16(C[0], mh[kc], Ah0, Ah1);
            mma16(C[1], mh[kc], Ah2, Ah3);
            mma16(C[2], mh[kc], Bh0, Bh1);
            mma16(C[3], mh[kc], Bh2, Bh3);
            mma16(C[0], mh[kc], Al0, Al1);
            mma16(C[1], mh[kc], Al2, Al3);
            mma16(C[2], mh[kc], Bl0, Bl1);
            mma16(C[3], mh[kc], Bl2, Bl3);
            mma16(C[0], ml[kc], Ah0, Ah1);
            mma16(C[1], ml[kc], Ah2, Ah3);
            mma16(C[2], ml[kc], Bh0, Bh1);
            mma16(C[3], ml[kc], Bh2, Bh3);
        }

        const int r0 = 16 * ms + g, r1 = r0 + 8;
#pragma unroll
        for (int nb = 0; nb < 4; ++nb) {
            const int n = s * TN + nh * 32 + nb * 8 + 2 * t;
            *reinterpret_cast<float2*>(ob + (size_t)r0 * NTOK + n) =
                make_float2(C[nb][0] + bias0, C[nb][1] + bias0);
            *reinterpret_cast<float2*>(ob + (size_t)r1 * NTOK + n) =
                make_float2(C[nb][2] + bias1, C[nb][3] + bias1);
        }
    }
}

extern "C" void kernel_launch(void* const* d_in, const int* in_sizes, int n_in,
                              void* d_out, int out_size)
{
    const float* x    = (const float*)d_in[0];
    const float* wqkv = (const float*)d_in[1];
    const float* wout = (const float*)d_in[2];
    const float* bout = (const float*)d_in[3];
    float* out = (float*)d_out;

    const int smem_k1 = (SREDOFF + 256) * 4;   // 103424 B
    const int smem_k3 = SREDOFF * 4;           // 102400 B
    cudaFuncSetAttribute(kv_ctx_kernel,   cudaFuncAttributeMaxDynamicSharedMemorySize, smem_k1);
    cudaFuncSetAttribute(out_proj_kernel, cudaFuncAttributeMaxDynamicSharedMemorySize, smem_k3);

    kv_ctx_kernel<<<BATCH * NPB, 512, smem_k1>>>(x, wqkv);
    reduce_G_kernel<<<BATCH * 32, 256>>>();
    proj_kernel<<<BATCH, 256>>>(wqkv, wout);
    out_proj_kernel<<<BATCH * NPB, 512, smem_k3>>>(x, bout, out);
}